// round 2
// baseline (speedup 1.0000x reference)
#include <cuda_runtime.h>

// MultiScaleProcessor: images [64,256,256,3] f32 ->
// out [64, 4(scales 32/64/128/256), 256, 256, 3] f32.
// Per scale: bilinear resize (jnp.linspace(0, 255, s) sampling) then
// centered zero-pad to 256x256.
//
// Grid mapping (no integer division for indexing):
//   blockIdx.x = output row y (0..255)
//   blockIdx.y = scale index  (0:32 1:64 2:128 3:256)
//   blockIdx.z = batch image  (0..63)
//   threadIdx.x = float4 index within the 3072-byte output row (0..191)
// Each thread writes exactly one float4; all branches are block-uniform
// except the interior x-range check.

#define IMG_H 256
#define IMG_W 256
#define C 3
#define FLOATS_PER_ROW (IMG_W * C)                 // 768
#define VEC_PER_ROW (FLOATS_PER_ROW / 4)           // 192
#define FLOATS_PER_PLANE (IMG_H * FLOATS_PER_ROW)  // 196608
#define VEC_PER_PLANE (FLOATS_PER_PLANE / 4)       // 49152

__global__ __launch_bounds__(VEC_PER_ROW) void msp_kernel(const float* __restrict__ in,
                                                          float* __restrict__ out) {
    const int y    = blockIdx.x;        // output row
    const int sidx = blockIdx.y;        // scale index
    const int b    = blockIdx.z;        // image
    const int vx   = threadIdx.x;       // float4 within row

    const float* __restrict__ img = in + (size_t)b * FLOATS_PER_PLANE;
    // out plane index = b*4 + sidx
    float4* __restrict__ orow = reinterpret_cast<float4*>(out)
        + ((size_t)(b * 4 + sidx) * IMG_H + y) * VEC_PER_ROW;

    if (sidx == 3) {
        // Native resolution: pure float4 row copy.
        orow[vx] = reinterpret_cast<const float4*>(img)[(size_t)y * VEC_PER_ROW + vx];
        return;
    }

    const int s = 32 << sidx;
    const int p = (IMG_H - s) >> 1;     // centered pad
    const int yi = y - p;

    if ((unsigned)yi >= (unsigned)s) {
        // Pad row: zero store only (block-uniform fast path).
        orow[vx] = make_float4(0.f, 0.f, 0.f, 0.f);
        return;
    }

    // Interior row: bilinear sample. Row-level values are block-uniform.
    const float step = 255.0f / (float)(s - 1);
    const float fy = (float)yi * step;
    const int   y0 = (int)fy;                       // fy >= 0: trunc == floor
    const float wy = fy - (float)y0;
    const int   y1 = min(y0 + 1, IMG_H - 1);
    const float* __restrict__ row0 = img + y0 * FLOATS_PER_ROW;
    const float* __restrict__ row1 = img + y1 * FLOATS_PER_ROW;
    const float omy = 1.0f - wy;

    float res[4];
    int f = vx * 4;                                  // float index within row
    #pragma unroll
    for (int k = 0; k < 4; ++k, ++f) {
        const int xo = f / 3;                        // output pixel x (const divisor -> mul)
        const int c  = f - xo * 3;                   // channel
        const int xi = xo - p;
        float val = 0.0f;
        if ((unsigned)xi < (unsigned)s) {
            const float fx = (float)xi * step;
            const int   x0 = (int)fx;
            const float wx = fx - (float)x0;
            const int   x1 = min(x0 + 1, IMG_W - 1);
            const float omx = 1.0f - wx;
            const int i00 = x0 * C + c;
            const int i01 = x1 * C + c;
            const float top = row0[i00] * omx + row0[i01] * wx;
            const float bot = row1[i00] * omx + row1[i01] * wx;
            val = top * omy + bot * wy;
        }
        res[k] = val;
    }
    orow[vx] = make_float4(res[0], res[1], res[2], res[3]);
}

extern "C" void kernel_launch(void* const* d_in, const int* in_sizes, int n_in,
                              void* d_out, int out_size) {
    const float* images = (const float*)d_in[0];
    float* out = (float*)d_out;
    dim3 grid(IMG_H, 4, 64);            // rows x scales x images = 65536 blocks
    dim3 block(VEC_PER_ROW);            // 192 threads, one float4 each
    msp_kernel<<<grid, block>>>(images, out);
}